// round 1
// baseline (speedup 1.0000x reference)
#include <cuda_runtime.h>

#define MROWS  16384
#define INDIM  1024
#define HDIM   512
#define DDIM   256
#define KCODES 4096
#define ODIM   1024

// ---------------- scratch (static device globals; no allocations) ----------
__device__ float g_h[(size_t)MROWS * HDIM];   // h = z @ W_qa + b_qa
__device__ float g_a[2][MROWS];               // |z_half|^2 per row
__device__ float g_bn[2][KCODES];             // |emb_k|^2 per code
__device__ int   g_idx[2][MROWS];             // argmin indices
__device__ float g_p[2][MROWS];               // winning squared distance

// ---------------- emb row norms: |e_k|^2 ----------------
__global__ void norms_kernel(const float* __restrict__ emb1,
                             const float* __restrict__ emb2) {
    int gw   = (blockIdx.x * blockDim.x + threadIdx.x) >> 5;
    int lane = threadIdx.x & 31;
    if (gw >= 2 * KCODES) return;
    int half = gw >> 12;                 // 4096 codes per half
    int k    = gw & (KCODES - 1);
    const float* row = (half ? emb2 : emb1) + (size_t)k * DDIM;
    float s = 0.0f;
    for (int c = lane; c < DDIM; c += 32) { float v = row[c]; s = __fmaf_rn(v, v, s); }
#pragma unroll
    for (int o = 16; o; o >>= 1) s += __shfl_xor_sync(0xffffffffu, s, o);
    if (lane == 0) g_bn[half][k] = s;
}

// ---------------- row norms of h halves: |z_half|^2 ----------------
__global__ void rownorm_kernel() {
    int gw   = (blockIdx.x * blockDim.x + threadIdx.x) >> 5;
    int lane = threadIdx.x & 31;
    if (gw >= MROWS) return;
    const float* row = g_h + (size_t)gw * HDIM;
#pragma unroll
    for (int half = 0; half < 2; half++) {
        float s = 0.0f;
        for (int c = lane; c < DDIM; c += 32) {
            float v = row[half * DDIM + c];
            s = __fmaf_rn(v, v, s);
        }
#pragma unroll
        for (int o = 16; o; o >>= 1) s += __shfl_xor_sync(0xffffffffu, s, o);
        if (lane == 0) g_a[half][gw] = s;
    }
}

// ---------------- GEMM1: g_h = z @ W_qa + b_qa  (M=16384,N=512,K=1024) -----
__global__ __launch_bounds__(256)
void gemm1_kernel(const float* __restrict__ A,   // z [M, 1024]
                  const float* __restrict__ B,   // W_qa [1024, 512]
                  const float* __restrict__ bias)// b_qa [512]
{
    __shared__ float As[8][128];
    __shared__ float Bs[8][128];
    const int tid   = threadIdx.x;
    const int m0    = blockIdx.y * 128;
    const int n0    = blockIdx.x * 128;
    const int a_row = tid >> 1;
    const int a_col = (tid & 1) << 2;
    const int b_row = tid >> 5;
    const int b_col = (tid & 31) << 2;
    const int ty    = tid >> 4;
    const int tx    = tid & 15;

    float acc[8][8];
#pragma unroll
    for (int i = 0; i < 8; i++)
#pragma unroll
        for (int j = 0; j < 8; j++) acc[i][j] = 0.0f;

    for (int k0 = 0; k0 < INDIM; k0 += 8) {
        float4 av = *(const float4*)(A + (size_t)(m0 + a_row) * INDIM + k0 + a_col);
        As[a_col + 0][a_row] = av.x;
        As[a_col + 1][a_row] = av.y;
        As[a_col + 2][a_row] = av.z;
        As[a_col + 3][a_row] = av.w;
        *(float4*)&Bs[b_row][b_col] =
            *(const float4*)(B + (size_t)(k0 + b_row) * HDIM + n0 + b_col);
        __syncthreads();
#pragma unroll
        for (int k = 0; k < 8; k++) {
            float ra[8], rb[8];
            *(float4*)&ra[0] = *(const float4*)&As[k][ty * 8];
            *(float4*)&ra[4] = *(const float4*)&As[k][ty * 8 + 4];
            *(float4*)&rb[0] = *(const float4*)&Bs[k][tx * 8];
            *(float4*)&rb[4] = *(const float4*)&Bs[k][tx * 8 + 4];
#pragma unroll
            for (int i = 0; i < 8; i++)
#pragma unroll
                for (int j = 0; j < 8; j++)
                    acc[i][j] = __fmaf_rn(ra[i], rb[j], acc[i][j]);
        }
        __syncthreads();
    }
#pragma unroll
    for (int i = 0; i < 8; i++) {
        int m = m0 + ty * 8 + i;
#pragma unroll
        for (int j = 0; j < 8; j += 4) {
            int n = n0 + tx * 8 + j;
            float4 o;
            o.x = acc[i][j + 0] + bias[n + 0];
            o.y = acc[i][j + 1] + bias[n + 1];
            o.z = acc[i][j + 2] + bias[n + 2];
            o.w = acc[i][j + 3] + bias[n + 3];
            *(float4*)(g_h + (size_t)m * HDIM + n) = o;
        }
    }
}

// ---------------- VQ: fused distance GEMM + argmin -------------------------
// d_k = fp32( fp32(|z|^2 + |e_k|^2) - fp32(2 * <z, e_k>) ), first-index ties.
__global__ __launch_bounds__(256)
void vq_kernel(const float* __restrict__ emb1,
               const float* __restrict__ emb2)
{
    __shared__ float As[8][128];
    __shared__ float Bs[8][128];
    __shared__ float sS[128][16];
    __shared__ int   sI[128][16];

    const int half = blockIdx.y;
    const float* __restrict__ emb = half ? emb2 : emb1;
    const int tid   = threadIdx.x;
    const int m0    = blockIdx.x * 128;
    const int a_row = tid >> 1;
    const int a_col = (tid & 1) << 2;
    const int ty    = tid >> 4;
    const int tx    = tid & 15;

    const float* Abase = g_h + (size_t)half * DDIM;

    float a_m[8];
#pragma unroll
    for (int i = 0; i < 8; i++) a_m[i] = g_a[half][m0 + ty * 8 + i];

    float best[8];
    int   bidx[8];
#pragma unroll
    for (int i = 0; i < 8; i++) { best[i] = __int_as_float(0x7f800000); bidx[i] = 0; }

    for (int n0 = 0; n0 < KCODES; n0 += 128) {
        float acc[8][8];
#pragma unroll
        for (int i = 0; i < 8; i++)
#pragma unroll
            for (int j = 0; j < 8; j++) acc[i][j] = 0.0f;

        for (int k0 = 0; k0 < DDIM; k0 += 8) {
            float4 av = *(const float4*)(Abase + (size_t)(m0 + a_row) * HDIM + k0 + a_col);
            As[a_col + 0][a_row] = av.x;
            As[a_col + 1][a_row] = av.y;
            As[a_col + 2][a_row] = av.z;
            As[a_col + 3][a_row] = av.w;
            float4 ev = *(const float4*)(emb + (size_t)(n0 + a_row) * DDIM + k0 + a_col);
            Bs[a_col + 0][a_row] = ev.x;
            Bs[a_col + 1][a_row] = ev.y;
            Bs[a_col + 2][a_row] = ev.z;
            Bs[a_col + 3][a_row] = ev.w;
            __syncthreads();
#pragma unroll
            for (int k = 0; k < 8; k++) {
                float ra[8], rb[8];
                *(float4*)&ra[0] = *(const float4*)&As[k][ty * 8];
                *(float4*)&ra[4] = *(const float4*)&As[k][ty * 8 + 4];
                *(float4*)&rb[0] = *(const float4*)&Bs[k][tx * 8];
                *(float4*)&rb[4] = *(const float4*)&Bs[k][tx * 8 + 4];
#pragma unroll
                for (int i = 0; i < 8; i++)
#pragma unroll
                    for (int j = 0; j < 8; j++)
                        acc[i][j] = __fmaf_rn(ra[i], rb[j], acc[i][j]);
            }
            __syncthreads();
        }

        float rbn[8];
#pragma unroll
        for (int j = 0; j < 8; j++) rbn[j] = g_bn[half][n0 + tx * 8 + j];
#pragma unroll
        for (int i = 0; i < 8; i++) {
#pragma unroll
            for (int j = 0; j < 8; j++) {
                float t  = __fadd_rn(a_m[i], rbn[j]);          // a + b   (fp32)
                float c2 = __fmul_rn(2.0f, acc[i][j]);         // 2*dot   (exact)
                float dd = __fadd_rn(t, -c2);                  // (a+b)-c (fp32, no FMA)
                if (dd < best[i]) { best[i] = dd; bidx[i] = n0 + tx * 8 + j; }
            }
        }
    }

#pragma unroll
    for (int i = 0; i < 8; i++) { sS[ty * 8 + i][tx] = best[i]; sI[ty * 8 + i][tx] = bidx[i]; }
    __syncthreads();
    if (tid < 128) {
        float b = sS[tid][0]; int bi = sI[tid][0];
#pragma unroll
        for (int t = 1; t < 16; t++) {
            float s = sS[tid][t]; int si = sI[tid][t];
            if (s < b || (s == b && si < bi)) { b = s; bi = si; }
        }
        int m = m0 + tid;
        g_idx[half][m] = bi;
        g_p[half][m]   = b;
    }
}

// ---------------- idx + loss outputs ----------------
__global__ void finalize_kernel(float* __restrict__ out) {
    int m = blockIdx.x * blockDim.x + threadIdx.x;
    if (m >= MROWS) return;
    const size_t ZQ = (size_t)MROWS * ODIM;
    out[ZQ + m]             = (float)g_idx[0][m];
    out[ZQ + MROWS + m]     = (float)g_idx[1][m];
    float m1 = __fmul_rn(g_p[0][m], 1.0f / 256.0f);
    float m2 = __fmul_rn(g_p[1][m], 1.0f / 256.0f);
    float l1 = __fadd_rn(m1, __fmul_rn(0.25f, m1));
    float l2 = __fadd_rn(m2, __fmul_rn(0.25f, m2));
    out[ZQ + 2 * (size_t)MROWS + m] = __fmul_rn(0.5f, __fadd_rn(l1, l2));
}

// ---------------- GEMM2: out = st(concat gather) @ W_pq + b_pq -------------
// straight-through replicated elementwise: zq_st = h + fp32(e - h)
__global__ __launch_bounds__(256)
void gemm2_kernel(const float* __restrict__ emb1,
                  const float* __restrict__ emb2,
                  const float* __restrict__ W,    // [512, 1024]
                  const float* __restrict__ bias, // [1024]
                  float* __restrict__ C)          // [M, 1024]
{
    __shared__ float As[8][128];
    __shared__ float Bs[8][128];
    __shared__ int   sIdx[2][128];
    const int tid   = threadIdx.x;
    const int m0    = blockIdx.y * 128;
    const int n0    = blockIdx.x * 128;
    const int a_row = tid >> 1;
    const int a_col = (tid & 1) << 2;
    const int b_row = tid >> 5;
    const int b_col = (tid & 31) << 2;
    const int ty    = tid >> 4;
    const int tx    = tid & 15;

    if (tid < 128) {
        sIdx[0][tid] = g_idx[0][m0 + tid];
        sIdx[1][tid] = g_idx[1][m0 + tid];
    }
    __syncthreads();

    float acc[8][8];
#pragma unroll
    for (int i = 0; i < 8; i++)
#pragma unroll
        for (int j = 0; j < 8; j++) acc[i][j] = 0.0f;

    for (int k0 = 0; k0 < HDIM; k0 += 8) {
        const int half = (k0 >= DDIM) ? 1 : 0;
        const float* e = half ? emb2 : emb1;
        int ridx = sIdx[half][a_row];
        int col  = k0 - half * DDIM + a_col;
        float4 ev = *(const float4*)(e + (size_t)ridx * DDIM + col);
        float4 hv = *(const float4*)(g_h + (size_t)(m0 + a_row) * HDIM + k0 + a_col);
        float4 sv;
        sv.x = __fadd_rn(hv.x, __fadd_rn(ev.x, -hv.x));
        sv.y = __fadd_rn(hv.y, __fadd_rn(ev.y, -hv.y));
        sv.z = __fadd_rn(hv.z, __fadd_rn(ev.z, -hv.z));
        sv.w = __fadd_rn(hv.w, __fadd_rn(ev.w, -hv.w));
        As[a_col + 0][a_row] = sv.x;
        As[a_col + 1][a_row] = sv.y;
        As[a_col + 2][a_row] = sv.z;
        As[a_col + 3][a_row] = sv.w;
        *(float4*)&Bs[b_row][b_col] =
            *(const float4*)(W + (size_t)(k0 + b_row) * ODIM + n0 + b_col);
        __syncthreads();
#pragma unroll
        for (int k = 0; k < 8; k++) {
            float ra[8], rb[8];
            *(float4*)&ra[0] = *(const float4*)&As[k][ty * 8];
            *(float4*)&ra[4] = *(const float4*)&As[k][ty * 8 + 4];
            *(float4*)&rb[0] = *(const float4*)&Bs[k][tx * 8];
            *(float4*)&rb[4] = *(const float4*)&Bs[k][tx * 8 + 4];
#pragma unroll
            for (int i = 0; i < 8; i++)
#pragma unroll
                for (int j = 0; j < 8; j++)
                    acc[i][j] = __fmaf_rn(ra[i], rb[j], acc[i][j]);
        }
        __syncthreads();
    }
#pragma unroll
    for (int i = 0; i < 8; i++) {
        int m = m0 + ty * 8 + i;
#pragma unroll
        for (int j = 0; j < 8; j += 4) {
            int n = n0 + tx * 8 + j;
            float4 o;
            o.x = acc[i][j + 0] + bias[n + 0];
            o.y = acc[i][j + 1] + bias[n + 1];
            o.z = acc[i][j + 2] + bias[n + 2];
            o.w = acc[i][j + 3] + bias[n + 3];
            *(float4*)(C + (size_t)m * ODIM + n) = o;
        }
    }
}

// ---------------- launch ----------------
extern "C" void kernel_launch(void* const* d_in, const int* in_sizes, int n_in,
                              void* d_out, int out_size) {
    (void)in_sizes; (void)n_in; (void)out_size;
    const float* z    = (const float*)d_in[0];
    const float* Wqa  = (const float*)d_in[1];
    const float* bqa  = (const float*)d_in[2];
    const float* emb1 = (const float*)d_in[3];
    const float* emb2 = (const float*)d_in[4];
    const float* Wpq  = (const float*)d_in[5];
    const float* bpq  = (const float*)d_in[6];
    float* out = (float*)d_out;

    norms_kernel<<<(2 * KCODES * 32 + 255) / 256, 256>>>(emb1, emb2);

    dim3 g1(HDIM / 128, MROWS / 128);
    gemm1_kernel<<<g1, 256>>>(z, Wqa, bqa);

    rownorm_kernel<<<(MROWS * 32 + 255) / 256, 256>>>();

    dim3 gv(MROWS / 128, 2);
    vq_kernel<<<gv, 256>>>(emb1, emb2);

    finalize_kernel<<<(MROWS + 255) / 256, 256>>>(out);

    dim3 g2(ODIM / 128, MROWS / 128);
    gemm2_kernel<<<g2, 256>>>(emb1, emb2, Wpq, bpq, out);
}

// round 6
// speedup vs baseline: 1.2323x; 1.2323x over previous
#include <cuda_runtime.h>
#include <cstdint>

#define MROWS  16384
#define INDIM  1024
#define HDIM   512
#define DDIM   256
#define KCODES 4096
#define ODIM   1024

typedef unsigned long long u64;

// ---------------- scratch (static device globals; no allocations) ----------
__device__ float g_h[(size_t)MROWS * HDIM];    // h = z @ W_qa + b_qa
__device__ float g_hT[(size_t)HDIM * MROWS];   // transposed h: [kk][m], kk = half*256+k
__device__ float g_eT[2][DDIM][KCODES];        // transposed emb: [half][k][n]
__device__ float g_a[2][MROWS];                // |z_half|^2 per row
__device__ float g_bn[2][KCODES];              // |emb_k|^2 per code
__device__ int   g_idx[2][MROWS];              // argmin indices
__device__ float g_p[2][MROWS];                // winning squared distance

// ---------------- f32x2 packed helpers (bitwise = two independent fp32 rn FMAs)
__device__ __forceinline__ u64 pk(float x, float y) {
    u64 r; asm("mov.b64 %0, {%1, %2};" : "=l"(r) : "f"(x), "f"(y)); return r;
}
__device__ __forceinline__ void upk(u64 v, float& x, float& y) {
    asm("mov.b64 {%0, %1}, %2;" : "=f"(x), "=f"(y) : "l"(v));
}
__device__ __forceinline__ void ffma2(u64& d, u64 a, u64 b) {
    asm("fma.rn.f32x2 %0, %1, %2, %0;" : "+l"(d) : "l"(a), "l"(b));
}
__device__ __forceinline__ uint32_t smem_u32(const void* p) {
    uint32_t a;
    asm("{ .reg .u64 t; cvta.to.shared.u64 t, %1; cvt.u32.u64 %0, t; }" : "=r"(a) : "l"(p));
    return a;
}
__device__ __forceinline__ void cp16(uint32_t dst, const void* src) {
    asm volatile("cp.async.ca.shared.global [%0], [%1], 16;" :: "r"(dst), "l"(src));
}
__device__ __forceinline__ void cp_commit() { asm volatile("cp.async.commit_group;"); }
template <int N> __device__ __forceinline__ void cp_wait() {
    asm volatile("cp.async.wait_group %0;" :: "n"(N));
}

// ---------------- emb row norms: |e_k|^2 (round-1 verbatim) ----------------
__global__ void norms_kernel(const float* __restrict__ emb1,
                             const float* __restrict__ emb2) {
    int gw   = (blockIdx.x * blockDim.x + threadIdx.x) >> 5;
    int lane = threadIdx.x & 31;
    if (gw >= 2 * KCODES) return;
    int half = gw >> 12;
    int k    = gw & (KCODES - 1);
    const float* row = (half ? emb2 : emb1) + (size_t)k * DDIM;
    float s = 0.0f;
    for (int c = lane; c < DDIM; c += 32) { float v = row[c]; s = __fmaf_rn(v, v, s); }
#pragma unroll
    for (int o = 16; o; o >>= 1) s += __shfl_xor_sync(0xffffffffu, s, o);
    if (lane == 0) g_bn[half][k] = s;
}

// ---------------- row norms of h halves (round-1 verbatim) ----------------
__global__ void rownorm_kernel() {
    int gw   = (blockIdx.x * blockDim.x + threadIdx.x) >> 5;
    int lane = threadIdx.x & 31;
    if (gw >= MROWS) return;
    const float* row = g_h + (size_t)gw * HDIM;
#pragma unroll
    for (int half = 0; half < 2; half++) {
        float s = 0.0f;
        for (int c = lane; c < DDIM; c += 32) {
            float v = row[half * DDIM + c];
            s = __fmaf_rn(v, v, s);
        }
#pragma unroll
        for (int o = 16; o; o >>= 1) s += __shfl_xor_sync(0xffffffffu, s, o);
        if (lane == 0) g_a[half][gw] = s;
    }
}

// ---------------- transposes ----------------
__global__ void transposeH_kernel() {           // g_hT[kk][m] = g_h[m][kk]
    __shared__ float t[32][33];
    int m0 = blockIdx.x * 32, k0 = blockIdx.y * 32;
    int x = threadIdx.x, y = threadIdx.y;
#pragma unroll
    for (int r = 0; r < 32; r += 8)
        t[y + r][x] = g_h[(size_t)(m0 + y + r) * HDIM + k0 + x];
    __syncthreads();
#pragma unroll
    for (int r = 0; r < 32; r += 8)
        g_hT[(size_t)(k0 + y + r) * MROWS + m0 + x] = t[x][y + r];
}
__global__ void transposeE_kernel(const float* __restrict__ emb1,
                                  const float* __restrict__ emb2) {
    __shared__ float t[32][33];
    int n0 = blockIdx.x * 32, k0 = blockIdx.y * 32, half = blockIdx.z;
    const float* E = half ? emb2 : emb1;
    int x = threadIdx.x, y = threadIdx.y;
#pragma unroll
    for (int r = 0; r < 32; r += 8)
        t[y + r][x] = E[(size_t)(n0 + y + r) * DDIM + k0 + x];
    __syncthreads();
#pragma unroll
    for (int r = 0; r < 32; r += 8)
        g_eT[half][k0 + y + r][n0 + x] = t[x][y + r];
}

// ---------------- shared f32x2 inner product step on one k-slice -----------
// a pairs cover rows (2ip, 2ip+1); b duplicated per column j.
__device__ __forceinline__ void fma_tile(u64 acc2[4][8],
                                         float4 a0, float4 a1,
                                         float4 b0, float4 b1) {
    u64 av[4] = { pk(a0.x, a0.y), pk(a0.z, a0.w), pk(a1.x, a1.y), pk(a1.z, a1.w) };
    float rb[8] = { b0.x, b0.y, b0.z, b0.w, b1.x, b1.y, b1.z, b1.w };
    u64 bd[8];
#pragma unroll
    for (int j = 0; j < 8; j++) bd[j] = pk(rb[j], rb[j]);
#pragma unroll
    for (int ip = 0; ip < 4; ip++)
#pragma unroll
        for (int j = 0; j < 8; j++) ffma2(acc2[ip][j], av[ip], bd[j]);
}

// ---------------- GEMM1: g_h = z @ W_qa + b_qa (round-1 structure, f32x2) --
__global__ __launch_bounds__(256)
void gemm1_kernel(const float* __restrict__ A, const float* __restrict__ B,
                  const float* __restrict__ bias) {
    __shared__ float As[8][128];
    __shared__ float Bs[8][128];
    const int tid   = threadIdx.x;
    const int m0    = blockIdx.y * 128;
    const int n0    = blockIdx.x * 128;
    const int a_row = tid >> 1;
    const int a_col = (tid & 1) << 2;
    const int b_row = tid >> 5;
    const int b_col = (tid & 31) << 2;
    const int ty    = tid >> 4;
    const int tx    = tid & 15;

    u64 acc2[4][8];
    const u64 Z = pk(0.0f, 0.0f);
#pragma unroll
    for (int ip = 0; ip < 4; ip++)
#pragma unroll
        for (int j = 0; j < 8; j++) acc2[ip][j] = Z;

    for (int k0 = 0; k0 < INDIM; k0 += 8) {
        float4 av = *(const float4*)(A + (size_t)(m0 + a_row) * INDIM + k0 + a_col);
        As[a_col + 0][a_row] = av.x;
        As[a_col + 1][a_row] = av.y;
        As[a_col + 2][a_row] = av.z;
        As[a_col + 3][a_row] = av.w;
        *(float4*)&Bs[b_row][b_col] =
            *(const float4*)(B + (size_t)(k0 + b_row) * HDIM + n0 + b_col);
        __syncthreads();
#pragma unroll
        for (int k = 0; k < 8; k++) {
            float4 a0 = *(const float4*)&As[k][ty * 8];
            float4 a1 = *(const float4*)&As[k][ty * 8 + 4];
            float4 b0 = *(const float4*)&Bs[k][tx * 8];
            float4 b1 = *(const float4*)&Bs[k][tx * 8 + 4];
            fma_tile(acc2, a0, a1, b0, b1);
        }
        __syncthreads();
    }
#pragma unroll
    for (int ip = 0; ip < 4; ip++) {
        float cx[8], cy[8];
#pragma unroll
        for (int j = 0; j < 8; j++) upk(acc2[ip][j], cx[j], cy[j]);
        int r0 = m0 + ty * 8 + 2 * ip;
#pragma unroll
        for (int j = 0; j < 8; j += 4) {
            int n = n0 + tx * 8 + j;
            float4 o0, o1;
            o0.x = cx[j+0] + bias[n+0]; o0.y = cx[j+1] + bias[n+1];
            o0.z = cx[j+2] + bias[n+2]; o0.w = cx[j+3] + bias[n+3];
            o1.x = cy[j+0] + bias[n+0]; o1.y = cy[j+1] + bias[n+1];
            o1.z = cy[j+2] + bias[n+2]; o1.w = cy[j+3] + bias[n+3];
            *(float4*)(g_h + (size_t)r0 * HDIM + n)       = o0;
            *(float4*)(g_h + (size_t)(r0 + 1) * HDIM + n) = o1;
        }
    }
}

// ---------------- VQ: cp.async double-buffered, f32x2, fused argmin --------
// Operands pre-transposed (k-major). k-chunk = 16. smem = 2 buffers x 16 KB.
__global__ __launch_bounds__(256, 2)
void vq_kernel() {
    __shared__ float sm[8192];   // buf b: A at b*4096, B at b*4096+2048
    const uint32_t smb = smem_u32(sm);
    const int tid = threadIdx.x;
    const int ty  = tid >> 4;
    const int tx  = tid & 15;
    const int half = blockIdx.y, m0 = blockIdx.x * 128;

    const float* __restrict__ AT = g_hT + (size_t)(half * DDIM) * MROWS + m0;
    const float* __restrict__ BT = &g_eT[half][0][0];
    const float* __restrict__ bn = &g_bn[half][0];

    float am[8];
#pragma unroll
    for (int i = 0; i < 8; i++) am[i] = g_a[half][m0 + ty * 8 + i];

    float best[8]; int bidx[8];
#pragma unroll
    for (int i = 0; i < 8; i++) { best[i] = __int_as_float(0x7f800000); bidx[i] = 0; }

    auto issue = [&](int c) {
        const int nt = c >> 4, kc = c & 15;
        const int n0 = nt * 128;
        const float* Asrc = AT + (size_t)(kc * 16) * MROWS;
        const float* Bsrc = BT + (size_t)(kc * 16) * KCODES + n0;
        uint32_t ab = smb + (uint32_t)((c & 1) * 4096) * 4;
        uint32_t bb = ab + 2048 * 4;
#pragma unroll
        for (int i = 0; i < 2; i++) {
            int f = tid + i * 256;
            int k = f >> 5, c4 = f & 31;
            cp16(ab + (uint32_t)(k * 128 + c4 * 4) * 4, Asrc + (size_t)k * MROWS + c4 * 4);
            cp16(bb + (uint32_t)(k * 128 + c4 * 4) * 4, Bsrc + (size_t)k * KCODES + c4 * 4);
        }
        cp_commit();
    };

    u64 acc2[4][8];
    const u64 Z = pk(0.0f, 0.0f);
    const int NCH = (KCODES / 128) * 16;   // 512 chunks

    issue(0);
    for (int c = 0; c < NCH; c++) {
        if (c + 1 < NCH) { issue(c + 1); cp_wait<1>(); } else { cp_wait<0>(); }
        __syncthreads();
        const int kc = c & 15;
        if (kc == 0) {
#pragma unroll
            for (int ip = 0; ip < 4; ip++)
#pragma unroll
                for (int j = 0; j < 8; j++) acc2[ip][j] = Z;
        }
        const float* buf = sm + (c & 1) * 4096;
#pragma unroll
        for (int k = 0; k < 16; k++) {
            float4 a0 = *(const float4*)(buf + k * 128 + ty * 8);
            float4 a1 = *(const float4*)(buf + k * 128 + ty * 8 + 4);
            float4 b0 = *(const float4*)(buf + 2048 + k * 128 + tx * 8);
            float4 b1 = *(const float4*)(buf + 2048 + k * 128 + tx * 8 + 4);
            fma_tile(acc2, a0, a1, b0, b1);
        }
        if (kc == 15) {
            const int n0 = (c >> 4) * 128;
            float bnv[8];
#pragma unroll
            for (int j = 0; j < 8; j++) bnv[j] = __ldg(bn + n0 + tx * 8 + j);
#pragma unroll
            for (int ip = 0; ip < 4; ip++) {
                int i0 = 2 * ip, i1 = 2 * ip + 1;
#pragma unroll
                for (int j = 0; j < 8; j++) {
                    float dx, dy;
                    upk(acc2[ip][j], dx, dy);
                    int col = n0 + tx * 8 + j;
                    float t0 = __fadd_rn(am[i0], bnv[j]);
                    float d0 = __fadd_rn(t0, -__fmul_rn(2.0f, dx));
                    if (d0 < best[i0]) { best[i0] = d0; bidx[i0] = col; }
                    float t1 = __fadd_rn(am[i1], bnv[j]);
                    float d1 = __fadd_rn(t1, -__fmul_rn(2.0f, dy));
                    if (d1 < best[i1]) { best[i1] = d1; bidx[i1] = col; }
                }
            }
        }
        __syncthreads();
    }

    // reduction (round-1 scheme), overlaid on smem buffers
    float* sS = sm;                  // [128][16]
    int*   sI = (int*)(sm + 2048);   // [128][16]
#pragma unroll
    for (int i = 0; i < 8; i++) {
        sS[(ty * 8 + i) * 16 + tx] = best[i];
        sI[(ty * 8 + i) * 16 + tx] = bidx[i];
    }
    __syncthreads();
    if (tid < 128) {
        float b = sS[tid * 16]; int bi = sI[tid * 16];
#pragma unroll
        for (int t = 1; t < 16; t++) {
            float s = sS[tid * 16 + t]; int si = sI[tid * 16 + t];
            if (s < b || (s == b && si < bi)) { b = s; bi = si; }
        }
        g_p[half][m0 + tid]   = b;
        g_idx[half][m0 + tid] = bi;
    }
}

// ---------------- idx + loss outputs (round-1 verbatim) ----------------
__global__ void finalize_kernel(float* __restrict__ out) {
    int m = blockIdx.x * blockDim.x + threadIdx.x;
    if (m >= MROWS) return;
    const size_t ZQ = (size_t)MROWS * ODIM;
    out[ZQ + m]             = (float)g_idx[0][m];
    out[ZQ + MROWS + m]     = (float)g_idx[1][m];
    float m1 = __fmul_rn(g_p[0][m], 1.0f / 256.0f);
    float m2 = __fmul_rn(g_p[1][m], 1.0f / 256.0f);
    float l1 = __fadd_rn(m1, __fmul_rn(0.25f, m1));
    float l2 = __fadd_rn(m2, __fmul_rn(0.25f, m2));
    out[ZQ + 2 * (size_t)MROWS + m] = __fmul_rn(0.5f, __fadd_rn(l1, l2));
}

// ---------------- GEMM2 (round-1 structure incl. inline zq_st, f32x2) ------
__global__ __launch_bounds__(256)
void gemm2_kernel(const float* __restrict__ emb1, const float* __restrict__ emb2,
                  const float* __restrict__ W, const float* __restrict__ bias,
                  float* __restrict__ C) {
    __shared__ float As[8][128];
    __shared__ float Bs[8][128];
    __shared__ int   sIdx[2][128];
    const int tid   = threadIdx.x;
    const int m0    = blockIdx.y * 128;
    const int n0    = blockIdx.x * 128;
    const int a_row = tid >> 1;
    const int a_col = (tid & 1) << 2;
    const int b_row = tid >> 5;
    const int b_col = (tid & 31) << 2;
    const int ty    = tid >> 4;
    const int tx    = tid & 15;

    if (tid < 128) {
        sIdx[0][tid] = g_idx[0][m0 + tid];
        sIdx[1][tid] = g_idx[1][m0 + tid];
    }
    __syncthreads();

    u64 acc2[4][8];
    const u64 Z = pk(0.0f, 0.0f);
#pragma unroll
    for (int ip = 0; ip < 4; ip++)
#pragma unroll
        for (int j = 0; j < 8; j++) acc2[ip][j] = Z;

    for (int k0 = 0; k0 < HDIM; k0 += 8) {
        const int half = (k0 >= DDIM) ? 1 : 0;
        const float* e = half ? emb2 : emb1;
        int ridx = sIdx[half][a_row];
        int col  = k0 - half * DDIM + a_col;
        float4 ev = *(const float4*)(e + (size_t)ridx * DDIM + col);
        float4 hv = *(const float4*)(g_h + (size_t)(m0 + a_row) * HDIM + k0 + a_col);
        float4 sv;
        sv.x = __fadd_rn(hv.x, __fadd_rn(ev.x, -hv.x));
        sv.y = __fadd_rn(hv.y, __fadd_rn(ev.y, -hv.y));
        sv.z = __fadd_rn(hv.z, __fadd_rn(ev.z, -hv.z));
        sv.w = __fadd_rn(hv.w, __fadd_rn(ev.w, -hv.w));
        As[a_col + 0][a_row] = sv.x;
        As[a_col + 1][a_row] = sv.y;
        As[a_col + 2][a_row] = sv.z;
        As[a_col + 3][a_row] = sv.w;
        *(float4*)&Bs[b_row][b_col] =
            *(const float4*)(W + (size_t)(k0 + b_row) * ODIM + n0 + b_col);
        __syncthreads();
#pragma unroll
        for (int k = 0; k < 8; k++) {
            float4 a0 = *(const float4*)&As[k][ty * 8];
            float4 a1 = *(const float4*)&As[k][ty * 8 + 4];
            float4 b0 = *(const float4*)&Bs[k][tx * 8];
            float4 b1 = *(const float4*)&Bs[k][tx * 8 + 4];
            fma_tile(acc2, a0, a1, b0, b1);
        }
        __syncthreads();
    }
#pragma unroll
    for (int ip = 0; ip < 4; ip++) {
        float cx[8], cy[8];
#pragma unroll
        for (int j = 0; j < 8; j++) upk(acc2[ip][j], cx[j], cy[j]);
        int r0 = m0 + ty * 8 + 2 * ip;
#pragma unroll
        for (int j = 0; j < 8; j += 4) {
            int n = n0 + tx * 8 + j;
            float4 o0, o1;
            o0.x = cx[j+0] + bias[n+0]; o0.y = cx[j+1] + bias[n+1];
            o0.z = cx[j+2] + bias[n+2]; o0.w = cx[j+3] + bias[n+3];
            o1.x = cy[j+0] + bias[n+0]; o1.y = cy[j+1] + bias[n+1];
            o1.z = cy[j+2] + bias[n+2]; o1.w = cy[j+3] + bias[n+3];
            *(float4*)(C + (size_t)r0 * ODIM + n)       = o0;
            *(float4*)(C + (size_t)(r0 + 1) * ODIM + n) = o1;
        }
    }
}

// ---------------- launch ----------------
extern "C" void kernel_launch(void* const* d_in, const int* in_sizes, int n_in,
                              void* d_out, int out_size) {
    (void)in_sizes; (void)n_in; (void)out_size;
    const float* z    = (const float*)d_in[0];
    const float* Wqa  = (const float*)d_in[1];
    const float* bqa  = (const float*)d_in[2];
    const float* emb1 = (const float*)d_in[3];
    const float* emb2 = (const float*)d_in[4];
    const float* Wpq  = (const float*)d_in[5];
    const float* bpq  = (const float*)d_in[6];
    float* out = (float*)d_out;

    norms_kernel<<<(2 * KCODES * 32 + 255) / 256, 256>>>(emb1, emb2);
    transposeE_kernel<<<dim3(KCODES / 32, DDIM / 32, 2), dim3(32, 8)>>>(emb1, emb2);

    dim3 g1(HDIM / 128, MROWS / 128);
    gemm1_kernel<<<g1, 256>>>(z, Wqa, bqa);

    transposeH_kernel<<<dim3(MROWS / 32, HDIM / 32), dim3(32, 8)>>>();
    rownorm_kernel<<<(MROWS * 32 + 255) / 256, 256>>>();

    vq_kernel<<<dim3(MROWS / 128, 2), 256>>>();

    finalize_kernel<<<(MROWS + 255) / 256, 256>>>(out);

    dim3 g2(ODIM / 128, MROWS / 128);
    gemm2_kernel<<<g2, 256>>>(emb1, emb2, Wpq, bpq, out);
}